// round 15
// baseline (speedup 1.0000x reference)
#include <cuda_runtime.h>
#include <cuda_bf16.h>
#include <math.h>
#include <stdint.h>

// Problem dims (fixed)
#define SEQ 256
#define BATCH 32
#define EDIM 256
#define HDIM 512
#define GDIM 2048           // 4*H
#define TTAGS 10
#define START_TAG 8
#define STOP_TAG 9
#define NEGV -10000.0f

// fast activations (MUFU-based; |err| ~1e-6, budget 1e-3)
__device__ __forceinline__ float fsig(float x)  { return 1.f / (1.f + __expf(-x)); }
__device__ __forceinline__ float ftanh(float x) { return 1.f - 2.f / (__expf(2.f * x) + 1.f); }

// ---------------- scratch (static device globals; no runtime alloc) ----------
__device__ float g_xg2[2u * 4 * (SEQ * BATCH) * HDIM];   // [d][gate][m][j]
__device__ float g_hseq[2u * SEQ * BATCH * HDIM];        // f32 h for feats
// h as pre-packed mma B-fragment words: slot = (d*SEQ+t)*2+bh, 4096 words/slot.
// word idx = slot*4096 + ktile*128 + lane*4 + q, q = nt*2+reg  (LDG.128-friendly).
// Slot 1024 = zeros (step 0).
__device__ uint32_t g_hfrag_hi[1025u * 4096u];
__device__ uint32_t g_hfrag_lo[1025u * 4096u];
__device__ float g_feats[SEQ * BATCH * TTAGS];
__device__ int   g_cnt[4 * 32];                          // group counters at [g*32]

// m16n8k16 bf16 HMMA (sm_80+ baseline PTX; compiles for compute_103)
__device__ __forceinline__ void mma16816(float* c, const uint32_t* a, const uint32_t* b) {
    asm volatile(
        "mma.sync.aligned.m16n8k16.row.col.f32.bf16.bf16.f32 "
        "{%0,%1,%2,%3}, {%4,%5,%6,%7}, {%8,%9}, {%0,%1,%2,%3};"
        : "+f"(c[0]), "+f"(c[1]), "+f"(c[2]), "+f"(c[3])
        : "r"(a[0]), "r"(a[1]), "r"(a[2]), "r"(a[3]), "r"(b[0]), "r"(b[1]));
}

// split 16 f32 -> 16 bf16 hi + 16 bf16 lo, stored as 2x uint4 each
__device__ __forceinline__ void split16(const float* f, __nv_bfloat16* hi, __nv_bfloat16* lo) {
    uint32_t hw[8], lw[8];
    #pragma unroll
    for (int q = 0; q < 8; q++) {
        __nv_bfloat16 h0 = __float2bfloat16(f[2 * q]);
        __nv_bfloat16 h1 = __float2bfloat16(f[2 * q + 1]);
        __nv_bfloat16 l0 = __float2bfloat16(f[2 * q]     - __bfloat162float(h0));
        __nv_bfloat16 l1 = __float2bfloat16(f[2 * q + 1] - __bfloat162float(h1));
        hw[q] = (uint32_t)__bfloat16_as_ushort(h0) | ((uint32_t)__bfloat16_as_ushort(h1) << 16);
        lw[q] = (uint32_t)__bfloat16_as_ushort(l0) | ((uint32_t)__bfloat16_as_ushort(l1) << 16);
    }
    ((uint4*)hi)[0] = make_uint4(hw[0], hw[1], hw[2], hw[3]);
    ((uint4*)hi)[1] = make_uint4(hw[4], hw[5], hw[6], hw[7]);
    ((uint4*)lo)[0] = make_uint4(lw[0], lw[1], lw[2], lw[3]);
    ((uint4*)lo)[1] = make_uint4(lw[4], lw[5], lw[6], lw[7]);
}

// ---------------------------------------------------------------------------
__global__ void dummy_kernel() {}   // keeps ncu -s 5 window on recur_kernel

// ---------------------------------------------------------------------------
// Kernel 1: xg2[d][gate][m][j] via split-bf16 HMMA, software-pipelined staging.
// Block 128(m) x 128(n), K=256 in 8 iters of 32. 8 warps (2m x 4n), warp 64x32.
// Iter i+1's global loads issue before iter i's MMA wall (latency hidden).
// Also resets the recurrence barrier counters.
// ---------------------------------------------------------------------------
__global__ void __launch_bounds__(256) xg_kernel(
    const int* __restrict__ tokens, const float* __restrict__ emb,
    const float* __restrict__ wf, const float* __restrict__ bf,
    const float* __restrict__ wb, const float* __restrict__ bb)
{
    const int bm = blockIdx.x;          // 64
    const int bn = blockIdx.y;          // 16
    const int dir = blockIdx.z;         // 2
    const int tid = threadIdx.x;

    if (bm == 0 && bn == 0 && dir == 0 && tid < 4) g_cnt[tid * 32] = 0;

    const float* wp   = dir ? wb : wf;
    const float* bias = dir ? bb : bf;

    __shared__ int rowtok[128];
    __shared__ __align__(16) __nv_bfloat16 sAhi[128 * 40];
    __shared__ __align__(16) __nv_bfloat16 sAlo[128 * 40];
    __shared__ __align__(16) __nv_bfloat16 sBhi[128 * 40];
    __shared__ __align__(16) __nv_bfloat16 sBlo[128 * 40];

    if (tid < 128) {
        int mg = bm * 128 + tid;                 // m = t*32 + b
        rowtok[tid] = tokens[(mg & 31) * SEQ + (mg >> 5)];
    }
    __syncthreads();

    const int w   = tid >> 5;
    const int lid = tid & 31;
    const int g   = lid >> 2;
    const int tq  = lid & 3;
    const int wm  = w & 1;              // warp m (2)
    const int wn  = w >> 1;             // warp n (4)

    float acc[4][4][4];
    #pragma unroll
    for (int mt = 0; mt < 4; mt++)
        #pragma unroll
        for (int nt = 0; nt < 4; nt++)
            #pragma unroll
            for (int q = 0; q < 4; q++) acc[mt][nt][q] = 0.f;

    const int r  = tid & 127;           // staging row
    const int kh = (tid >> 7) * 16;     // staging k-half

    const float* arow = emb + (size_t)rowtok[r] * EDIM + kh;
    const float* brow = wp + (size_t)(bn * 128 + r) * EDIM + kh;

    // preload iteration 0
    float4 va[4], vb[4];
    #pragma unroll
    for (int i = 0; i < 4; i++) {
        va[i] = *(const float4*)(arow + 4 * i);
        vb[i] = *(const float4*)(brow + 4 * i);
    }

    for (int it = 0; it < 8; it++) {
        // ---- split current registers into smem ----
        {
            float fa[16], fb2[16];
            #pragma unroll
            for (int i = 0; i < 4; i++) {
                fa[4 * i] = va[i].x; fa[4 * i + 1] = va[i].y;
                fa[4 * i + 2] = va[i].z; fa[4 * i + 3] = va[i].w;
                fb2[4 * i] = vb[i].x; fb2[4 * i + 1] = vb[i].y;
                fb2[4 * i + 2] = vb[i].z; fb2[4 * i + 3] = vb[i].w;
            }
            split16(fa, sAhi + r * 40 + kh, sAlo + r * 40 + kh);
            split16(fb2, sBhi + r * 40 + kh, sBlo + r * 40 + kh);
        }
        __syncthreads();

        // ---- prefetch next iteration (issues before the MMA wall) ----
        if (it < 7) {
            const int k0n = (it + 1) * 32;
            #pragma unroll
            for (int i = 0; i < 4; i++) {
                va[i] = *(const float4*)(arow + k0n + 4 * i);
                vb[i] = *(const float4*)(brow + k0n + 4 * i);
            }
        }

        // ---- compute current iteration ----
        #pragma unroll
        for (int kk = 0; kk < 2; kk++) {
            const int kb = kk * 16;
            uint32_t Ah[4][4], Al[4][4], Bh[4][2], Bl[4][2];
            #pragma unroll
            for (int mt = 0; mt < 4; mt++) {
                int o = (wm * 64 + mt * 16 + g) * 40 + kb + 2 * tq;
                Ah[mt][0] = *(const uint32_t*)(sAhi + o);
                Ah[mt][1] = *(const uint32_t*)(sAhi + o + 8 * 40);
                Ah[mt][2] = *(const uint32_t*)(sAhi + o + 8);
                Ah[mt][3] = *(const uint32_t*)(sAhi + o + 8 * 40 + 8);
                Al[mt][0] = *(const uint32_t*)(sAlo + o);
                Al[mt][1] = *(const uint32_t*)(sAlo + o + 8 * 40);
                Al[mt][2] = *(const uint32_t*)(sAlo + o + 8);
                Al[mt][3] = *(const uint32_t*)(sAlo + o + 8 * 40 + 8);
            }
            #pragma unroll
            for (int nt = 0; nt < 4; nt++) {
                int o = (wn * 32 + nt * 8 + g) * 40 + kb + 2 * tq;
                Bh[nt][0] = *(const uint32_t*)(sBhi + o);
                Bh[nt][1] = *(const uint32_t*)(sBhi + o + 8);
                Bl[nt][0] = *(const uint32_t*)(sBlo + o);
                Bl[nt][1] = *(const uint32_t*)(sBlo + o + 8);
            }
            #pragma unroll
            for (int mt = 0; mt < 4; mt++)
                #pragma unroll
                for (int nt = 0; nt < 4; nt++) {
                    mma16816(acc[mt][nt], Ah[mt], Bh[nt]);
                    mma16816(acc[mt][nt], Ah[mt], Bl[nt]);
                    mma16816(acc[mt][nt], Al[mt], Bh[nt]);
                }
        }
        __syncthreads();
    }

    // ---- epilogue: add bias, store f32 (full 32B sectors per (g,nt)) ----
    const int gate  = bn >> 2;
    const int jbase = (bn & 3) * 128 + wn * 32;
    #pragma unroll
    for (int nt = 0; nt < 4; nt++) {
        int j = jbase + nt * 8 + 2 * tq;
        int nglob = bn * 128 + wn * 32 + nt * 8 + 2 * tq;
        float b0 = bias[nglob], b1 = bias[nglob + 1];
        #pragma unroll
        for (int mt = 0; mt < 4; mt++) {
            int m = bm * 128 + wm * 64 + mt * 16 + g;
            float* p0 = g_xg2 + (((size_t)dir * 4 + gate) * 8192 + m) * HDIM + j;
            float* p1 = p0 + 8 * HDIM;   // row m+8
            *(float2*)p0 = make_float2(acc[mt][nt][0] + b0, acc[mt][nt][1] + b1);
            *(float2*)p1 = make_float2(acc[mt][nt][2] + b0, acc[mt][nt][3] + b1);
        }
    }
}

// ---------------------------------------------------------------------------
// Kernel 2: persistent BiLSTM recurrence on HMMA (unchanged from R12).
// ---------------------------------------------------------------------------
__global__ void __launch_bounds__(256, 1) recur_kernel(
    const float* __restrict__ whhf, const float* __restrict__ whhb)
{
    __shared__ float part[8 * 64 * 17];   // [w][row 0..63][b 0..15] padded

    const int tid = threadIdx.x;
    const int w   = tid >> 5;
    const int lid = tid & 31;
    const int g   = lid >> 2;             // mma groupID
    const int tq  = lid & 3;              // mma threadID_in_group

    const int bid   = blockIdx.x;
    const int dir   = bid >> 6;
    const int sub   = bid & 63;
    const int chunk = sub >> 1;            // 0..31, 16 units each
    const int bh    = sub & 1;
    const int j0    = chunk * 16;

    // cell role: one (u, bt) per thread
    const int u  = tid & 15;
    const int bt = tid >> 4;

    int* cnt = g_cnt + (dir * 2 + bh) * 32;

    // ---- one-time: W fragments (hi/lo split) into registers ----
    const float* whh = dir ? whhb : whhf;
    uint32_t ahi[4][4][4], alo[4][4][4];   // [mt=gate][kt][reg]
    #pragma unroll
    for (int mt = 0; mt < 4; mt++)
        #pragma unroll
        for (int kt = 0; kt < 4; kt++)
            #pragma unroll
            for (int reg = 0; reg < 4; reg++) {
                int urow = g + (reg & 1) * 8;              // within 16-unit tile
                int grow = mt * HDIM + j0 + urow;          // row in W[2048]
                int k    = w * 64 + kt * 16 + 2 * tq + (reg >> 1) * 8;
                float v0 = whh[(size_t)grow * HDIM + k];
                float v1 = whh[(size_t)grow * HDIM + k + 1];
                __nv_bfloat16 h0 = __float2bfloat16(v0);
                __nv_bfloat16 h1 = __float2bfloat16(v1);
                __nv_bfloat16 l0 = __float2bfloat16(v0 - __bfloat162float(h0));
                __nv_bfloat16 l1 = __float2bfloat16(v1 - __bfloat162float(h1));
                ahi[mt][kt][reg] = (uint32_t)__bfloat16_as_ushort(h0)
                                 | ((uint32_t)__bfloat16_as_ushort(h1) << 16);
                alo[mt][kt][reg] = (uint32_t)__bfloat16_as_ushort(l0)
                                 | ((uint32_t)__bfloat16_as_ushort(l1) << 16);
            }

    float c = 0.f;                         // cell state (dir, j0+u, bh*16+bt)

    for (int step = 0; step < SEQ; ++step) {
        const int t = dir ? (SEQ - 1 - step) : step;

        // ---- group barrier: REDG arrive; ALL lanes acquire-poll (same addr) ----
        __syncthreads();                   // h-frag stores of prev step done CTA-wide
        if (tid == 0)
            asm volatile("red.release.gpu.global.add.s32 [%0], %1;" :: "l"(cnt), "r"(1) : "memory");

        // xg prefetch (independent of h; issues before the poll loop)
        float xgv[4];
        #pragma unroll
        for (int gate = 0; gate < 4; gate++)
            xgv[gate] = __ldg(g_xg2 +
                ((size_t)(dir * 4 + gate) * 8192 + (size_t)t * 32 + bh * 16 + bt) * HDIM + j0 + u);

        {
            const int target = 32 * (step + 1);
            int v;
            do {
                asm volatile("ld.acquire.gpu.global.s32 %0, [%1];" : "=r"(v) : "l"(cnt) : "memory");
            } while (v < target);
        }

        // ---- load B fragments: 4 hi + 4 lo LDG.128 per thread ----
        const uint32_t slot = (step == 0) ? 1024u
            : (uint32_t)((dir * SEQ + (dir ? t + 1 : t - 1)) * 2 + bh);
        const uint4* bhp = (const uint4*)(g_hfrag_hi + (size_t)slot * 4096u) + (w * 4) * 32 + lid;
        const uint4* blp = (const uint4*)(g_hfrag_lo + (size_t)slot * 4096u) + (w * 4) * 32 + lid;
        uint32_t bhi[4][2][2], blo[4][2][2];
        #pragma unroll
        for (int kt = 0; kt < 4; kt++) {
            uint4 vh = bhp[kt * 32];
            uint4 vl = blp[kt * 32];
            bhi[kt][0][0] = vh.x; bhi[kt][0][1] = vh.y;
            bhi[kt][1][0] = vh.z; bhi[kt][1][1] = vh.w;
            blo[kt][0][0] = vl.x; blo[kt][0][1] = vl.y;
            blo[kt][1][0] = vl.z; blo[kt][1][1] = vl.w;
        }

        // ---- MMAs: (Whi+Wlo)(hhi+hlo) minus lo*lo ----
        float acc[4][2][4];
        #pragma unroll
        for (int mt = 0; mt < 4; mt++)
            #pragma unroll
            for (int nt = 0; nt < 2; nt++)
                #pragma unroll
                for (int q = 0; q < 4; q++) acc[mt][nt][q] = 0.f;
        #pragma unroll
        for (int kt = 0; kt < 4; kt++)
            #pragma unroll
            for (int mt = 0; mt < 4; mt++)
                #pragma unroll
                for (int nt = 0; nt < 2; nt++) {
                    mma16816(acc[mt][nt], ahi[mt][kt], bhi[kt][nt]);
                    mma16816(acc[mt][nt], ahi[mt][kt], blo[kt][nt]);
                    mma16816(acc[mt][nt], alo[mt][kt], bhi[kt][nt]);
                }

        // ---- write partials to smem ----
        #pragma unroll
        for (int mt = 0; mt < 4; mt++)
            #pragma unroll
            for (int nt = 0; nt < 2; nt++) {
                int row0 = mt * 16 + g;
                int col0 = nt * 8 + 2 * tq;
                part[(w * 64 + row0) * 17 + col0]         = acc[mt][nt][0];
                part[(w * 64 + row0) * 17 + col0 + 1]     = acc[mt][nt][1];
                part[(w * 64 + row0 + 8) * 17 + col0]     = acc[mt][nt][2];
                part[(w * 64 + row0 + 8) * 17 + col0 + 1] = acc[mt][nt][3];
            }
        __syncthreads();

        // ---- reduce across 8 k-slices + LSTM cell for (u, bt) ----
        float gi = xgv[0], gf = xgv[1], gg = xgv[2], go = xgv[3];
        #pragma unroll
        for (int kw = 0; kw < 8; kw++) {
            gi += part[(kw * 64 +  0 + u) * 17 + bt];
            gf += part[(kw * 64 + 16 + u) * 17 + bt];
            gg += part[(kw * 64 + 32 + u) * 17 + bt];
            go += part[(kw * 64 + 48 + u) * 17 + bt];
        }
        c = fsig(gf) * c + fsig(gi) * ftanh(gg);
        float h = fsig(go) * ftanh(c);

        g_hseq[((size_t)(dir * SEQ + t) * BATCH + bh * 16 + bt) * HDIM + j0 + u] = h;

        // ---- pack h into B-fragment words (pairs along u via shfl) ----
        float ho = __shfl_xor_sync(0xffffffffu, h, 1);   // partner u^1, same bt
        if ((u & 1) == 0) {
            __nv_bfloat16 hh0 = __float2bfloat16(h);
            __nv_bfloat16 hh1 = __float2bfloat16(ho);
            __nv_bfloat16 hl0 = __float2bfloat16(h  - __bfloat162float(hh0));
            __nv_bfloat16 hl1 = __float2bfloat16(ho - __bfloat162float(hh1));
            uint32_t whi = (uint32_t)__bfloat16_as_ushort(hh0)
                         | ((uint32_t)__bfloat16_as_ushort(hh1) << 16);
            uint32_t wlo = (uint32_t)__bfloat16_as_ushort(hl0)
                         | ((uint32_t)__bfloat16_as_ushort(hl1) << 16);
            int reg = u >> 3;
            int tq2 = (u & 7) >> 1;
            int nt2 = bt >> 3;
            int g2  = bt & 7;
            uint32_t slotW = (uint32_t)((dir * SEQ + t) * 2 + bh);
            size_t idx = (size_t)slotW * 4096u + (uint32_t)chunk * 128u
                       + (uint32_t)((g2 * 4 + tq2) * 4 + nt2 * 2 + reg);
            g_hfrag_hi[idx] = whi;
            g_hfrag_lo[idx] = wlo;
        }
    }
}

// ---------------------------------------------------------------------------
// Kernel 3: feats (unchanged)
// ---------------------------------------------------------------------------
__global__ void __launch_bounds__(256) feats_kernel(
    const float* __restrict__ w_out, const float* __restrict__ b_out)
{
    const int s = blockIdx.x;
    const int w = threadIdx.x >> 5;
    const int l = threadIdx.x & 31;

    for (int b = w; b < BATCH; b += 8) {
        const float* hf = g_hseq + ((size_t)(0 * SEQ + s) * BATCH + b) * HDIM;
        const float* hb = g_hseq + ((size_t)(1 * SEQ + s) * BATCH + b) * HDIM;
        float hv[32];
        #pragma unroll
        for (int i = 0; i < 16; i++) hv[i]      = hf[l + 32 * i];
        #pragma unroll
        for (int i = 0; i < 16; i++) hv[16 + i] = hb[l + 32 * i];
        for (int tag = 0; tag < TTAGS; tag++) {
            const float* wr = w_out + (size_t)tag * (2 * HDIM);
            float p = 0.f;
            #pragma unroll
            for (int i = 0; i < 16; i++) p = fmaf(hv[i],      wr[l + 32 * i],        p);
            #pragma unroll
            for (int i = 0; i < 16; i++) p = fmaf(hv[16 + i], wr[HDIM + l + 32 * i], p);
            #pragma unroll
            for (int o = 16; o; o >>= 1) p += __shfl_down_sync(0xffffffffu, p, o);
            if (l == 0) g_feats[(s * BATCH + b) * TTAGS + tag] = p + b_out[tag];
        }
    }
}

// ---------------------------------------------------------------------------
// Kernel 4: CRF forward (MUFU exp/log in the serial scan)
// ---------------------------------------------------------------------------
__global__ void __launch_bounds__(32) crf_kernel(
    const int* __restrict__ lengths, const float* __restrict__ trans,
    float* __restrict__ out)
{
    const int b = blockIdx.x;
    const int l = threadIdx.x;

    __shared__ float fb[SEQ * TTAGS];
    __shared__ float es[32];
    for (int i = l; i < SEQ * TTAGS; i += 32) {
        int s = i / TTAGS, tg = i - s * TTAGS;
        fb[i] = g_feats[(s * BATCH + b) * TTAGS + tg];
    }

    float et[TTAGS];
    if (l < TTAGS) {
        #pragma unroll
        for (int p = 0; p < TTAGS; p++) et[p] = __expf(trans[l * TTAGS + p]);
    }
    float fv = (l == START_TAG) ? 0.f : NEGV;
    es[l] = 0.f;
    __syncwarp();

    const int len = lengths[b];
    for (int s = 0; s < len; s++) {
        float v = (l < TTAGS) ? fv : -1e30f;
        #pragma unroll
        for (int o = 8; o; o >>= 1) v = fmaxf(v, __shfl_xor_sync(0xffffffffu, v, o));
        float e = (l < TTAGS) ? __expf(fv - v) : 0.f;
        es[l] = e;
        __syncwarp();
        float sa = 0.f, sb = 0.f;
        #pragma unroll
        for (int p = 0; p < TTAGS; p += 2) {
            sa = fmaf(es[p],     et[p],     sa);
            sb = fmaf(es[p + 1], et[p + 1], sb);
        }
        if (l < TTAGS) fv = v + __logf(sa + sb) + fb[s * TTAGS + l];
        __syncwarp();
    }

    float term = (l < TTAGS) ? (fv + trans[STOP_TAG * TTAGS + l]) : -1e30f;
    float mx = term;
    #pragma unroll
    for (int o = 16; o; o >>= 1) mx = fmaxf(mx, __shfl_xor_sync(0xffffffffu, mx, o));
    float e = (l < TTAGS) ? __expf(term - mx) : 0.f;
    #pragma unroll
    for (int o = 16; o; o >>= 1) e += __shfl_xor_sync(0xffffffffu, e, o);
    if (l == 0) out[b] = (mx + __logf(e)) / (float)len;
}

// ---------------------------------------------------------------------------
extern "C" void kernel_launch(void* const* d_in, const int* in_sizes, int n_in,
                              void* d_out, int out_size)
{
    const int*   tokens  = (const int*)  d_in[0];
    const int*   lengths = (const int*)  d_in[1];
    const float* emb     = (const float*)d_in[2];
    const float* w_ih_f  = (const float*)d_in[3];
    const float* w_hh_f  = (const float*)d_in[4];
    const float* b_f     = (const float*)d_in[5];
    const float* w_ih_b  = (const float*)d_in[6];
    const float* w_hh_b  = (const float*)d_in[7];
    const float* b_b     = (const float*)d_in[8];
    const float* w_out   = (const float*)d_in[9];
    const float* b_out   = (const float*)d_in[10];
    const float* trans   = (const float*)d_in[11];
    float* out = (float*)d_out;

    dummy_kernel<<<1, 32>>>();
    dummy_kernel<<<1, 32>>>();
    xg_kernel<<<dim3(64, 16, 2), 256>>>(tokens, emb, w_ih_f, b_f, w_ih_b, b_b);
    recur_kernel<<<128, 256>>>(w_hh_f, w_hh_b);
    feats_kernel<<<SEQ, 256>>>(w_out, b_out);
    crf_kernel<<<BATCH, 32>>>(lengths, trans, out);
}

// round 16
// speedup vs baseline: 1.5621x; 1.5621x over previous
#include <cuda_runtime.h>
#include <cuda_bf16.h>
#include <math.h>
#include <stdint.h>

// Problem dims (fixed)
#define SEQ 256
#define BATCH 32
#define EDIM 256
#define HDIM 512
#define GDIM 2048           // 4*H
#define TTAGS 10
#define START_TAG 8
#define STOP_TAG 9
#define NEGV -10000.0f

// fast activations (MUFU-based; |err| ~1e-6, budget 1e-3)
__device__ __forceinline__ float fsig(float x)  { return 1.f / (1.f + __expf(-x)); }
__device__ __forceinline__ float ftanh(float x) { return 1.f - 2.f / (__expf(2.f * x) + 1.f); }

// ---------------- scratch (static device globals; no runtime alloc) ----------
__device__ float g_xg2[2u * 4 * (SEQ * BATCH) * HDIM];   // [d][gate][m][j]
__device__ float g_hseq[2u * SEQ * BATCH * HDIM];        // f32 h for feats
// h as pre-packed mma B-fragment words: slot = (d*SEQ+t)*2+bh, 4096 words/slot.
// word idx = slot*4096 + ktile*128 + lane*4 + q, q = nt*2+reg  (LDG.128-friendly).
// Slot 1024 = zeros (step 0).
__device__ uint32_t g_hfrag_hi[1025u * 4096u];
__device__ uint32_t g_hfrag_lo[1025u * 4096u];
__device__ float g_feats[SEQ * BATCH * TTAGS];
__device__ int   g_cnt[4 * 32];                          // group counters at [g*32]

// m16n8k16 bf16 HMMA (sm_80+ baseline PTX; compiles for compute_103)
__device__ __forceinline__ void mma16816(float* c, const uint32_t* a, const uint32_t* b) {
    asm volatile(
        "mma.sync.aligned.m16n8k16.row.col.f32.bf16.bf16.f32 "
        "{%0,%1,%2,%3}, {%4,%5,%6,%7}, {%8,%9}, {%0,%1,%2,%3};"
        : "+f"(c[0]), "+f"(c[1]), "+f"(c[2]), "+f"(c[3])
        : "r"(a[0]), "r"(a[1]), "r"(a[2]), "r"(a[3]), "r"(b[0]), "r"(b[1]));
}

// split 16 f32 -> 16 bf16 hi + 16 bf16 lo, stored as 2x uint4 each
__device__ __forceinline__ void split16(const float* f, __nv_bfloat16* hi, __nv_bfloat16* lo) {
    uint32_t hw[8], lw[8];
    #pragma unroll
    for (int q = 0; q < 8; q++) {
        __nv_bfloat16 h0 = __float2bfloat16(f[2 * q]);
        __nv_bfloat16 h1 = __float2bfloat16(f[2 * q + 1]);
        __nv_bfloat16 l0 = __float2bfloat16(f[2 * q]     - __bfloat162float(h0));
        __nv_bfloat16 l1 = __float2bfloat16(f[2 * q + 1] - __bfloat162float(h1));
        hw[q] = (uint32_t)__bfloat16_as_ushort(h0) | ((uint32_t)__bfloat16_as_ushort(h1) << 16);
        lw[q] = (uint32_t)__bfloat16_as_ushort(l0) | ((uint32_t)__bfloat16_as_ushort(l1) << 16);
    }
    ((uint4*)hi)[0] = make_uint4(hw[0], hw[1], hw[2], hw[3]);
    ((uint4*)hi)[1] = make_uint4(hw[4], hw[5], hw[6], hw[7]);
    ((uint4*)lo)[0] = make_uint4(lw[0], lw[1], lw[2], lw[3]);
    ((uint4*)lo)[1] = make_uint4(lw[4], lw[5], lw[6], lw[7]);
}

__device__ __forceinline__ uint32_t smem_u32(const void* p) {
    uint32_t a;
    asm("{ .reg .u64 t; cvta.to.shared.u64 t, %1; cvt.u32.u64 %0, t; }" : "=r"(a) : "l"(p));
    return a;
}
__device__ __forceinline__ void cp16(uint32_t dst, const void* src) {
    asm volatile("cp.async.ca.shared.global [%0], [%1], 16;" :: "r"(dst), "l"(src));
}
#define CP_COMMIT() asm volatile("cp.async.commit_group;" ::: "memory")
#define CP_WAIT0()  asm volatile("cp.async.wait_group 0;" ::: "memory")

// xg dynamic smem layout (bytes)
#define XSA_HI   0          // 128*40 bf16 = 10240
#define XSA_LO   10240
#define XSB_HI   20480
#define XSB_LO   30720
#define XSTAGE_A 40960      // 128*36 f32 = 18432 (stride 36: conflict-free LDS.128)
#define XSTAGE_B 59392
#define XG_SMEM  77824

// ---------------------------------------------------------------------------
__global__ void dummy_kernel() {}   // keeps ncu -s 5 window on recur_kernel

// ---------------------------------------------------------------------------
// Kernel 1: xg2[d][gate][m][j] via split-bf16 HMMA, cp.async-pipelined staging.
// Block 128(m) x 128(n), K=256 in 8 iters of 32. 8 warps (2m x 4n), warp 64x32.
// Iter i+1's cp.async overlaps iter i's MMA wall; no register-held prefetch.
// Also resets the recurrence barrier counters.
// ---------------------------------------------------------------------------
__global__ void __launch_bounds__(256) xg_kernel(
    const int* __restrict__ tokens, const float* __restrict__ emb,
    const float* __restrict__ wf, const float* __restrict__ bf,
    const float* __restrict__ wb, const float* __restrict__ bb)
{
    extern __shared__ __align__(16) char xsm[];
    __nv_bfloat16* sAhi = (__nv_bfloat16*)(xsm + XSA_HI);
    __nv_bfloat16* sAlo = (__nv_bfloat16*)(xsm + XSA_LO);
    __nv_bfloat16* sBhi = (__nv_bfloat16*)(xsm + XSB_HI);
    __nv_bfloat16* sBlo = (__nv_bfloat16*)(xsm + XSB_LO);
    float* sAf = (float*)(xsm + XSTAGE_A);
    float* sBf = (float*)(xsm + XSTAGE_B);

    const int bm = blockIdx.x;          // 64
    const int bn = blockIdx.y;          // 16
    const int dir = blockIdx.z;         // 2
    const int tid = threadIdx.x;

    if (bm == 0 && bn == 0 && dir == 0 && tid < 4) g_cnt[tid * 32] = 0;

    const float* wp   = dir ? wb : wf;
    const float* bias = dir ? bb : bf;

    __shared__ int rowtok[128];
    if (tid < 128) {
        int mg = bm * 128 + tid;                 // m = t*32 + b
        rowtok[tid] = tokens[(mg & 31) * SEQ + (mg >> 5)];
    }
    __syncthreads();

    const int w   = tid >> 5;
    const int lid = tid & 31;
    const int g   = lid >> 2;
    const int tq  = lid & 3;
    const int wm  = w & 1;              // warp m (2)
    const int wn  = w >> 1;             // warp n (4)

    float acc[4][4][4];
    #pragma unroll
    for (int mt = 0; mt < 4; mt++)
        #pragma unroll
        for (int nt = 0; nt < 4; nt++)
            #pragma unroll
            for (int q = 0; q < 4; q++) acc[mt][nt][q] = 0.f;

    // staging copy role: thread covers row crow, quarters [cq, cq+4) (16B each)
    const int crow = tid >> 1;
    const int cq   = (tid & 1) * 4;
    const float* arow = emb + (size_t)rowtok[crow] * EDIM;
    const float* brow = wp + (size_t)(bn * 128 + crow) * EDIM;
    const uint32_t adst = smem_u32(sAf) + (uint32_t)(crow * 144 + cq * 16);
    const uint32_t bdst = smem_u32(sBf) + (uint32_t)(crow * 144 + cq * 16);

    // split role
    const int r  = tid & 127;           // split row
    const int kh = (tid >> 7) * 16;     // split k-half

    // issue iteration 0
    #pragma unroll
    for (int q = 0; q < 4; q++) {
        cp16(adst + q * 16, arow + (cq + q) * 4);
        cp16(bdst + q * 16, brow + (cq + q) * 4);
    }
    CP_COMMIT();

    for (int it = 0; it < 8; it++) {
        CP_WAIT0();
        __syncthreads();                // all copies visible block-wide

        // ---- split f32 stage -> bf16 hi/lo tiles ----
        {
            float fa[16], fb2[16];
            const float4* ap = (const float4*)(sAf + r * 36 + kh);
            const float4* bp = (const float4*)(sBf + r * 36 + kh);
            #pragma unroll
            for (int i = 0; i < 4; i++) {
                float4 va = ap[i];
                fa[4 * i] = va.x; fa[4 * i + 1] = va.y; fa[4 * i + 2] = va.z; fa[4 * i + 3] = va.w;
                float4 vb = bp[i];
                fb2[4 * i] = vb.x; fb2[4 * i + 1] = vb.y; fb2[4 * i + 2] = vb.z; fb2[4 * i + 3] = vb.w;
            }
            split16(fa, sAhi + r * 40 + kh, sAlo + r * 40 + kh);
            split16(fb2, sBhi + r * 40 + kh, sBlo + r * 40 + kh);
        }
        __syncthreads();                // stage free, bf16 tiles ready

        // ---- issue next iteration's copies (overlap the MMA wall) ----
        if (it < 7) {
            const int k0n = (it + 1) * 32;
            #pragma unroll
            for (int q = 0; q < 4; q++) {
                cp16(adst + q * 16, arow + k0n + (cq + q) * 4);
                cp16(bdst + q * 16, brow + k0n + (cq + q) * 4);
            }
            CP_COMMIT();
        }

        // ---- compute current iteration ----
        #pragma unroll
        for (int kk = 0; kk < 2; kk++) {
            const int kb = kk * 16;
            uint32_t Ah[4][4], Al[4][4], Bh[4][2], Bl[4][2];
            #pragma unroll
            for (int mt = 0; mt < 4; mt++) {
                int o = (wm * 64 + mt * 16 + g) * 40 + kb + 2 * tq;
                Ah[mt][0] = *(const uint32_t*)(sAhi + o);
                Ah[mt][1] = *(const uint32_t*)(sAhi + o + 8 * 40);
                Ah[mt][2] = *(const uint32_t*)(sAhi + o + 8);
                Ah[mt][3] = *(const uint32_t*)(sAhi + o + 8 * 40 + 8);
                Al[mt][0] = *(const uint32_t*)(sAlo + o);
                Al[mt][1] = *(const uint32_t*)(sAlo + o + 8 * 40);
                Al[mt][2] = *(const uint32_t*)(sAlo + o + 8);
                Al[mt][3] = *(const uint32_t*)(sAlo + o + 8 * 40 + 8);
            }
            #pragma unroll
            for (int nt = 0; nt < 4; nt++) {
                int o = (wn * 32 + nt * 8 + g) * 40 + kb + 2 * tq;
                Bh[nt][0] = *(const uint32_t*)(sBhi + o);
                Bh[nt][1] = *(const uint32_t*)(sBhi + o + 8);
                Bl[nt][0] = *(const uint32_t*)(sBlo + o);
                Bl[nt][1] = *(const uint32_t*)(sBlo + o + 8);
            }
            #pragma unroll
            for (int mt = 0; mt < 4; mt++)
                #pragma unroll
                for (int nt = 0; nt < 4; nt++) {
                    mma16816(acc[mt][nt], Ah[mt], Bh[nt]);
                    mma16816(acc[mt][nt], Ah[mt], Bl[nt]);
                    mma16816(acc[mt][nt], Al[mt], Bh[nt]);
                }
        }
        __syncthreads();                // bf16 tiles consumed before next split
    }

    // ---- epilogue: add bias, store f32 (full 32B sectors per (g,nt)) ----
    const int gate  = bn >> 2;
    const int jbase = (bn & 3) * 128 + wn * 32;
    #pragma unroll
    for (int nt = 0; nt < 4; nt++) {
        int j = jbase + nt * 8 + 2 * tq;
        int nglob = bn * 128 + wn * 32 + nt * 8 + 2 * tq;
        float b0 = bias[nglob], b1 = bias[nglob + 1];
        #pragma unroll
        for (int mt = 0; mt < 4; mt++) {
            int m = bm * 128 + wm * 64 + mt * 16 + g;
            float* p0 = g_xg2 + (((size_t)dir * 4 + gate) * 8192 + m) * HDIM + j;
            float* p1 = p0 + 8 * HDIM;   // row m+8
            *(float2*)p0 = make_float2(acc[mt][nt][0] + b0, acc[mt][nt][1] + b1);
            *(float2*)p1 = make_float2(acc[mt][nt][2] + b0, acc[mt][nt][3] + b1);
        }
    }
}

// ---------------------------------------------------------------------------
// Kernel 2: persistent BiLSTM recurrence on HMMA (unchanged from R12/R13).
// ---------------------------------------------------------------------------
__global__ void __launch_bounds__(256, 1) recur_kernel(
    const float* __restrict__ whhf, const float* __restrict__ whhb)
{
    __shared__ float part[8 * 64 * 17];   // [w][row 0..63][b 0..15] padded

    const int tid = threadIdx.x;
    const int w   = tid >> 5;
    const int lid = tid & 31;
    const int g   = lid >> 2;             // mma groupID
    const int tq  = lid & 3;              // mma threadID_in_group

    const int bid   = blockIdx.x;
    const int dir   = bid >> 6;
    const int sub   = bid & 63;
    const int chunk = sub >> 1;            // 0..31, 16 units each
    const int bh    = sub & 1;
    const int j0    = chunk * 16;

    // cell role: one (u, bt) per thread
    const int u  = tid & 15;
    const int bt = tid >> 4;

    int* cnt = g_cnt + (dir * 2 + bh) * 32;

    // ---- one-time: W fragments (hi/lo split) into registers ----
    const float* whh = dir ? whhb : whhf;
    uint32_t ahi[4][4][4], alo[4][4][4];   // [mt=gate][kt][reg]
    #pragma unroll
    for (int mt = 0; mt < 4; mt++)
        #pragma unroll
        for (int kt = 0; kt < 4; kt++)
            #pragma unroll
            for (int reg = 0; reg < 4; reg++) {
                int urow = g + (reg & 1) * 8;              // within 16-unit tile
                int grow = mt * HDIM + j0 + (urow);        // row in W[2048]
                int k    = w * 64 + kt * 16 + 2 * tq + (reg >> 1) * 8;
                float v0 = whh[(size_t)grow * HDIM + k];
                float v1 = whh[(size_t)grow * HDIM + k + 1];
                __nv_bfloat16 h0 = __float2bfloat16(v0);
                __nv_bfloat16 h1 = __float2bfloat16(v1);
                __nv_bfloat16 l0 = __float2bfloat16(v0 - __bfloat162float(h0));
                __nv_bfloat16 l1 = __float2bfloat16(v1 - __bfloat162float(h1));
                ahi[mt][kt][reg] = (uint32_t)__bfloat16_as_ushort(h0)
                                 | ((uint32_t)__bfloat16_as_ushort(h1) << 16);
                alo[mt][kt][reg] = (uint32_t)__bfloat16_as_ushort(l0)
                                 | ((uint32_t)__bfloat16_as_ushort(l1) << 16);
            }

    float c = 0.f;                         // cell state (dir, j0+u, bh*16+bt)

    for (int step = 0; step < SEQ; ++step) {
        const int t = dir ? (SEQ - 1 - step) : step;

        // ---- group barrier: REDG arrive; ALL lanes acquire-poll (same addr) ----
        __syncthreads();                   // h-frag stores of prev step done CTA-wide
        if (tid == 0)
            asm volatile("red.release.gpu.global.add.s32 [%0], %1;" :: "l"(cnt), "r"(1) : "memory");

        // xg prefetch (independent of h; issues before the poll loop)
        float xgv[4];
        #pragma unroll
        for (int gate = 0; gate < 4; gate++)
            xgv[gate] = __ldg(g_xg2 +
                ((size_t)(dir * 4 + gate) * 8192 + (size_t)t * 32 + bh * 16 + bt) * HDIM + j0 + u);

        {
            const int target = 32 * (step + 1);
            int v;
            do {
                asm volatile("ld.acquire.gpu.global.s32 %0, [%1];" : "=r"(v) : "l"(cnt) : "memory");
            } while (v < target);
        }

        // ---- load B fragments: 4 hi + 4 lo LDG.128 per thread ----
        const uint32_t slot = (step == 0) ? 1024u
            : (uint32_t)((dir * SEQ + (dir ? t + 1 : t - 1)) * 2 + bh);
        const uint4* bhp = (const uint4*)(g_hfrag_hi + (size_t)slot * 4096u) + (w * 4) * 32 + lid;
        const uint4* blp = (const uint4*)(g_hfrag_lo + (size_t)slot * 4096u) + (w * 4) * 32 + lid;
        uint32_t bhi[4][2][2], blo[4][2][2];
        #pragma unroll
        for (int kt = 0; kt < 4; kt++) {
            uint4 vh = bhp[kt * 32];
            uint4 vl = blp[kt * 32];
            bhi[kt][0][0] = vh.x; bhi[kt][0][1] = vh.y;
            bhi[kt][1][0] = vh.z; bhi[kt][1][1] = vh.w;
            blo[kt][0][0] = vl.x; blo[kt][0][1] = vl.y;
            blo[kt][1][0] = vl.z; blo[kt][1][1] = vl.w;
        }

        // ---- MMAs: (Whi+Wlo)(hhi+hlo) minus lo*lo ----
        float acc[4][2][4];
        #pragma unroll
        for (int mt = 0; mt < 4; mt++)
            #pragma unroll
            for (int nt = 0; nt < 2; nt++)
                #pragma unroll
                for (int q = 0; q < 4; q++) acc[mt][nt][q] = 0.f;
        #pragma unroll
        for (int kt = 0; kt < 4; kt++)
            #pragma unroll
            for (int mt = 0; mt < 4; mt++)
                #pragma unroll
                for (int nt = 0; nt < 2; nt++) {
                    mma16816(acc[mt][nt], ahi[mt][kt], bhi[kt][nt]);
                    mma16816(acc[mt][nt], ahi[mt][kt], blo[kt][nt]);
                    mma16816(acc[mt][nt], alo[mt][kt], bhi[kt][nt]);
                }

        // ---- write partials to smem ----
        #pragma unroll
        for (int mt = 0; mt < 4; mt++)
            #pragma unroll
            for (int nt = 0; nt < 2; nt++) {
                int row0 = mt * 16 + g;
                int col0 = nt * 8 + 2 * tq;
                part[(w * 64 + row0) * 17 + col0]         = acc[mt][nt][0];
                part[(w * 64 + row0) * 17 + col0 + 1]     = acc[mt][nt][1];
                part[(w * 64 + row0 + 8) * 17 + col0]     = acc[mt][nt][2];
                part[(w * 64 + row0 + 8) * 17 + col0 + 1] = acc[mt][nt][3];
            }
        __syncthreads();

        // ---- reduce across 8 k-slices + LSTM cell for (u, bt) ----
        float gi = xgv[0], gf = xgv[1], gg = xgv[2], go = xgv[3];
        #pragma unroll
        for (int kw = 0; kw < 8; kw++) {
            gi += part[(kw * 64 +  0 + u) * 17 + bt];
            gf += part[(kw * 64 + 16 + u) * 17 + bt];
            gg += part[(kw * 64 + 32 + u) * 17 + bt];
            go += part[(kw * 64 + 48 + u) * 17 + bt];
        }
        c = fsig(gf) * c + fsig(gi) * ftanh(gg);
        float h = fsig(go) * ftanh(c);

        g_hseq[((size_t)(dir * SEQ + t) * BATCH + bh * 16 + bt) * HDIM + j0 + u] = h;

        // ---- pack h into B-fragment words (pairs along u via shfl) ----
        float ho = __shfl_xor_sync(0xffffffffu, h, 1);   // partner u^1, same bt
        if ((u & 1) == 0) {
            __nv_bfloat16 hh0 = __float2bfloat16(h);
            __nv_bfloat16 hh1 = __float2bfloat16(ho);
            __nv_bfloat16 hl0 = __float2bfloat16(h  - __bfloat162float(hh0));
            __nv_bfloat16 hl1 = __float2bfloat16(ho - __bfloat162float(hh1));
            uint32_t whi = (uint32_t)__bfloat16_as_ushort(hh0)
                         | ((uint32_t)__bfloat16_as_ushort(hh1) << 16);
            uint32_t wlo = (uint32_t)__bfloat16_as_ushort(hl0)
                         | ((uint32_t)__bfloat16_as_ushort(hl1) << 16);
            int reg = u >> 3;
            int tq2 = (u & 7) >> 1;
            int nt2 = bt >> 3;
            int g2  = bt & 7;
            uint32_t slotW = (uint32_t)((dir * SEQ + t) * 2 + bh);
            size_t idx = (size_t)slotW * 4096u + (uint32_t)chunk * 128u
                       + (uint32_t)((g2 * 4 + tq2) * 4 + nt2 * 2 + reg);
            g_hfrag_hi[idx] = whi;
            g_hfrag_lo[idx] = wlo;
        }
    }
}

// ---------------------------------------------------------------------------
// Kernel 3: feats (unchanged)
// ---------------------------------------------------------------------------
__global__ void __launch_bounds__(256) feats_kernel(
    const float* __restrict__ w_out, const float* __restrict__ b_out)
{
    const int s = blockIdx.x;
    const int w = threadIdx.x >> 5;
    const int l = threadIdx.x & 31;

    for (int b = w; b < BATCH; b += 8) {
        const float* hf = g_hseq + ((size_t)(0 * SEQ + s) * BATCH + b) * HDIM;
        const float* hb = g_hseq + ((size_t)(1 * SEQ + s) * BATCH + b) * HDIM;
        float hv[32];
        #pragma unroll
        for (int i = 0; i < 16; i++) hv[i]      = hf[l + 32 * i];
        #pragma unroll
        for (int i = 0; i < 16; i++) hv[16 + i] = hb[l + 32 * i];
        for (int tag = 0; tag < TTAGS; tag++) {
            const float* wr = w_out + (size_t)tag * (2 * HDIM);
            float p = 0.f;
            #pragma unroll
            for (int i = 0; i < 16; i++) p = fmaf(hv[i],      wr[l + 32 * i],        p);
            #pragma unroll
            for (int i = 0; i < 16; i++) p = fmaf(hv[16 + i], wr[HDIM + l + 32 * i], p);
            #pragma unroll
            for (int o = 16; o; o >>= 1) p += __shfl_down_sync(0xffffffffu, p, o);
            if (l == 0) g_feats[(s * BATCH + b) * TTAGS + tag] = p + b_out[tag];
        }
    }
}

// ---------------------------------------------------------------------------
// Kernel 4: CRF forward (MUFU exp/log in the serial scan)
// ---------------------------------------------------------------------------
__global__ void __launch_bounds__(32) crf_kernel(
    const int* __restrict__ lengths, const float* __restrict__ trans,
    float* __restrict__ out)
{
    const int b = blockIdx.x;
    const int l = threadIdx.x;

    __shared__ float fb[SEQ * TTAGS];
    __shared__ float es[32];
    for (int i = l; i < SEQ * TTAGS; i += 32) {
        int s = i / TTAGS, tg = i - s * TTAGS;
        fb[i] = g_feats[(s * BATCH + b) * TTAGS + tg];
    }

    float et[TTAGS];
    if (l < TTAGS) {
        #pragma unroll
        for (int p = 0; p < TTAGS; p++) et[p] = __expf(trans[l * TTAGS + p]);
    }
    float fv = (l == START_TAG) ? 0.f : NEGV;
    es[l] = 0.f;
    __syncwarp();

    const int len = lengths[b];
    for (int s = 0; s < len; s++) {
        float v = (l < TTAGS) ? fv : -1e30f;
        #pragma unroll
        for (int o = 8; o; o >>= 1) v = fmaxf(v, __shfl_xor_sync(0xffffffffu, v, o));
        float e = (l < TTAGS) ? __expf(fv - v) : 0.f;
        es[l] = e;
        __syncwarp();
        float sa = 0.f, sb = 0.f;
        #pragma unroll
        for (int p = 0; p < TTAGS; p += 2) {
            sa = fmaf(es[p],     et[p],     sa);
            sb = fmaf(es[p + 1], et[p + 1], sb);
        }
        if (l < TTAGS) fv = v + __logf(sa + sb) + fb[s * TTAGS + l];
        __syncwarp();
    }

    float term = (l < TTAGS) ? (fv + trans[STOP_TAG * TTAGS + l]) : -1e30f;
    float mx = term;
    #pragma unroll
    for (int o = 16; o; o >>= 1) mx = fmaxf(mx, __shfl_xor_sync(0xffffffffu, mx, o));
    float e = (l < TTAGS) ? __expf(term - mx) : 0.f;
    #pragma unroll
    for (int o = 16; o; o >>= 1) e += __shfl_xor_sync(0xffffffffu, e, o);
    if (l == 0) out[b] = (mx + __logf(e)) / (float)len;
}

// ---------------------------------------------------------------------------
extern "C" void kernel_launch(void* const* d_in, const int* in_sizes, int n_in,
                              void* d_out, int out_size)
{
    const int*   tokens  = (const int*)  d_in[0];
    const int*   lengths = (const int*)  d_in[1];
    const float* emb     = (const float*)d_in[2];
    const float* w_ih_f  = (const float*)d_in[3];
    const float* w_hh_f  = (const float*)d_in[4];
    const float* b_f     = (const float*)d_in[5];
    const float* w_ih_b  = (const float*)d_in[6];
    const float* w_hh_b  = (const float*)d_in[7];
    const float* b_b     = (const float*)d_in[8];
    const float* w_out   = (const float*)d_in[9];
    const float* b_out   = (const float*)d_in[10];
    const float* trans   = (const float*)d_in[11];
    float* out = (float*)d_out;

    cudaFuncSetAttribute(xg_kernel, cudaFuncAttributeMaxDynamicSharedMemorySize, XG_SMEM);

    dummy_kernel<<<1, 32>>>();
    dummy_kernel<<<1, 32>>>();
    xg_kernel<<<dim3(64, 16, 2), 256, XG_SMEM>>>(tokens, emb, w_ih_f, b_f, w_ih_b, b_b);
    recur_kernel<<<128, 256>>>(w_hh_f, w_hh_b);
    feats_kernel<<<SEQ, 256>>>(w_out, b_out);
    crf_kernel<<<BATCH, 32>>>(lengths, trans, out);
}

// round 17
// speedup vs baseline: 1.6236x; 1.0394x over previous
#include <cuda_runtime.h>
#include <cuda_bf16.h>
#include <math.h>
#include <stdint.h>

// Problem dims (fixed)
#define SEQ 256
#define BATCH 32
#define EDIM 256
#define HDIM 512
#define GDIM 2048           // 4*H
#define TTAGS 10
#define START_TAG 8
#define STOP_TAG 9
#define NEGV -10000.0f

// fast activations (MUFU-based; |err| ~1e-6, budget 1e-3)
__device__ __forceinline__ float fsig(float x)  { return 1.f / (1.f + __expf(-x)); }
__device__ __forceinline__ float ftanh(float x) { return 1.f - 2.f / (__expf(2.f * x) + 1.f); }

// ---------------- scratch (static device globals; no runtime alloc) ----------
__device__ float g_xg2[2u * 4 * (SEQ * BATCH) * HDIM];   // [d][gate][m][j]
__device__ float g_hseq[2u * SEQ * BATCH * HDIM];        // f32 h for feats
// h as pre-packed mma B-fragment words: slot = (d*SEQ+t)*2+bh, 4096 words/slot.
// word idx = slot*4096 + ktile*128 + lane*4 + q, q = nt*2+reg  (LDG.128-friendly).
// Slot 1024 = zeros (step 0).
__device__ uint32_t g_hfrag_hi[1025u * 4096u];
__device__ uint32_t g_hfrag_lo[1025u * 4096u];
__device__ float g_feats[SEQ * BATCH * TTAGS];
// sub-group barrier counters: [(dir*2+bh)*8 + sg] at stride 32 ints (128B)
__device__ int   g_scnt[32 * 32];

// m16n8k16 bf16 HMMA (sm_80+ baseline PTX; compiles for compute_103)
__device__ __forceinline__ void mma16816(float* c, const uint32_t* a, const uint32_t* b) {
    asm volatile(
        "mma.sync.aligned.m16n8k16.row.col.f32.bf16.bf16.f32 "
        "{%0,%1,%2,%3}, {%4,%5,%6,%7}, {%8,%9}, {%0,%1,%2,%3};"
        : "+f"(c[0]), "+f"(c[1]), "+f"(c[2]), "+f"(c[3])
        : "r"(a[0]), "r"(a[1]), "r"(a[2]), "r"(a[3]), "r"(b[0]), "r"(b[1]));
}

// split 16 f32 -> 16 bf16 hi + 16 bf16 lo, stored as 2x uint4 each
__device__ __forceinline__ void split16(const float* f, __nv_bfloat16* hi, __nv_bfloat16* lo) {
    uint32_t hw[8], lw[8];
    #pragma unroll
    for (int q = 0; q < 8; q++) {
        __nv_bfloat16 h0 = __float2bfloat16(f[2 * q]);
        __nv_bfloat16 h1 = __float2bfloat16(f[2 * q + 1]);
        __nv_bfloat16 l0 = __float2bfloat16(f[2 * q]     - __bfloat162float(h0));
        __nv_bfloat16 l1 = __float2bfloat16(f[2 * q + 1] - __bfloat162float(h1));
        hw[q] = (uint32_t)__bfloat16_as_ushort(h0) | ((uint32_t)__bfloat16_as_ushort(h1) << 16);
        lw[q] = (uint32_t)__bfloat16_as_ushort(l0) | ((uint32_t)__bfloat16_as_ushort(l1) << 16);
    }
    ((uint4*)hi)[0] = make_uint4(hw[0], hw[1], hw[2], hw[3]);
    ((uint4*)hi)[1] = make_uint4(hw[4], hw[5], hw[6], hw[7]);
    ((uint4*)lo)[0] = make_uint4(lw[0], lw[1], lw[2], lw[3]);
    ((uint4*)lo)[1] = make_uint4(lw[4], lw[5], lw[6], lw[7]);
}

__device__ __forceinline__ uint32_t smem_u32(const void* p) {
    uint32_t a;
    asm("{ .reg .u64 t; cvta.to.shared.u64 t, %1; cvt.u32.u64 %0, t; }" : "=r"(a) : "l"(p));
    return a;
}
__device__ __forceinline__ void cp16(uint32_t dst, const void* src) {
    asm volatile("cp.async.ca.shared.global [%0], [%1], 16;" :: "r"(dst), "l"(src));
}
#define CP_COMMIT() asm volatile("cp.async.commit_group;" ::: "memory")
#define CP_WAIT0()  asm volatile("cp.async.wait_group 0;" ::: "memory")

// xg dynamic smem layout (bytes)
#define XSA_HI   0          // 128*40 bf16 = 10240
#define XSA_LO   10240
#define XSB_HI   20480
#define XSB_LO   30720
#define XSTAGE_A 40960      // 128*36 f32 = 18432 (stride 36: conflict-free LDS.128)
#define XSTAGE_B 59392
#define XG_SMEM  77824

// ---------------------------------------------------------------------------
__global__ void dummy_kernel() {}   // keeps ncu -s 5 window on recur_kernel

// ---------------------------------------------------------------------------
// Kernel 1: xg2[d][gate][m][j] via split-bf16 HMMA, cp.async-pipelined staging.
// (R15-proven.) Also resets the recurrence sub-group barrier counters.
// ---------------------------------------------------------------------------
__global__ void __launch_bounds__(256) xg_kernel(
    const int* __restrict__ tokens, const float* __restrict__ emb,
    const float* __restrict__ wf, const float* __restrict__ bf,
    const float* __restrict__ wb, const float* __restrict__ bb)
{
    extern __shared__ __align__(16) char xsm[];
    __nv_bfloat16* sAhi = (__nv_bfloat16*)(xsm + XSA_HI);
    __nv_bfloat16* sAlo = (__nv_bfloat16*)(xsm + XSA_LO);
    __nv_bfloat16* sBhi = (__nv_bfloat16*)(xsm + XSB_HI);
    __nv_bfloat16* sBlo = (__nv_bfloat16*)(xsm + XSB_LO);
    float* sAf = (float*)(xsm + XSTAGE_A);
    float* sBf = (float*)(xsm + XSTAGE_B);

    const int bm = blockIdx.x;          // 64
    const int bn = blockIdx.y;          // 16
    const int dir = blockIdx.z;         // 2
    const int tid = threadIdx.x;

    if (bm == 0 && bn == 0 && dir == 0 && tid < 32) g_scnt[tid * 32] = 0;

    const float* wp   = dir ? wb : wf;
    const float* bias = dir ? bb : bf;

    __shared__ int rowtok[128];
    if (tid < 128) {
        int mg = bm * 128 + tid;                 // m = t*32 + b
        rowtok[tid] = tokens[(mg & 31) * SEQ + (mg >> 5)];
    }
    __syncthreads();

    const int w   = tid >> 5;
    const int lid = tid & 31;
    const int g   = lid >> 2;
    const int tq  = lid & 3;
    const int wm  = w & 1;              // warp m (2)
    const int wn  = w >> 1;             // warp n (4)

    float acc[4][4][4];
    #pragma unroll
    for (int mt = 0; mt < 4; mt++)
        #pragma unroll
        for (int nt = 0; nt < 4; nt++)
            #pragma unroll
            for (int q = 0; q < 4; q++) acc[mt][nt][q] = 0.f;

    // staging copy role: thread covers row crow, quarters [cq, cq+4) (16B each)
    const int crow = tid >> 1;
    const int cq   = (tid & 1) * 4;
    const float* arow = emb + (size_t)rowtok[crow] * EDIM;
    const float* brow = wp + (size_t)(bn * 128 + crow) * EDIM;
    const uint32_t adst = smem_u32(sAf) + (uint32_t)(crow * 144 + cq * 16);
    const uint32_t bdst = smem_u32(sBf) + (uint32_t)(crow * 144 + cq * 16);

    // split role
    const int r  = tid & 127;           // split row
    const int kh = (tid >> 7) * 16;     // split k-half

    // issue iteration 0
    #pragma unroll
    for (int q = 0; q < 4; q++) {
        cp16(adst + q * 16, arow + (cq + q) * 4);
        cp16(bdst + q * 16, brow + (cq + q) * 4);
    }
    CP_COMMIT();

    for (int it = 0; it < 8; it++) {
        CP_WAIT0();
        __syncthreads();                // all copies visible block-wide

        // ---- split f32 stage -> bf16 hi/lo tiles ----
        {
            float fa[16], fb2[16];
            const float4* ap = (const float4*)(sAf + r * 36 + kh);
            const float4* bp = (const float4*)(sBf + r * 36 + kh);
            #pragma unroll
            for (int i = 0; i < 4; i++) {
                float4 va = ap[i];
                fa[4 * i] = va.x; fa[4 * i + 1] = va.y; fa[4 * i + 2] = va.z; fa[4 * i + 3] = va.w;
                float4 vb = bp[i];
                fb2[4 * i] = vb.x; fb2[4 * i + 1] = vb.y; fb2[4 * i + 2] = vb.z; fb2[4 * i + 3] = vb.w;
            }
            split16(fa, sAhi + r * 40 + kh, sAlo + r * 40 + kh);
            split16(fb2, sBhi + r * 40 + kh, sBlo + r * 40 + kh);
        }
        __syncthreads();                // stage free, bf16 tiles ready

        // ---- issue next iteration's copies (overlap the MMA wall) ----
        if (it < 7) {
            const int k0n = (it + 1) * 32;
            #pragma unroll
            for (int q = 0; q < 4; q++) {
                cp16(adst + q * 16, arow + k0n + (cq + q) * 4);
                cp16(bdst + q * 16, brow + k0n + (cq + q) * 4);
            }
            CP_COMMIT();
        }

        // ---- compute current iteration ----
        #pragma unroll
        for (int kk = 0; kk < 2; kk++) {
            const int kb = kk * 16;
            uint32_t Ah[4][4], Al[4][4], Bh[4][2], Bl[4][2];
            #pragma unroll
            for (int mt = 0; mt < 4; mt++) {
                int o = (wm * 64 + mt * 16 + g) * 40 + kb + 2 * tq;
                Ah[mt][0] = *(const uint32_t*)(sAhi + o);
                Ah[mt][1] = *(const uint32_t*)(sAhi + o + 8 * 40);
                Ah[mt][2] = *(const uint32_t*)(sAhi + o + 8);
                Ah[mt][3] = *(const uint32_t*)(sAhi + o + 8 * 40 + 8);
                Al[mt][0] = *(const uint32_t*)(sAlo + o);
                Al[mt][1] = *(const uint32_t*)(sAlo + o + 8 * 40);
                Al[mt][2] = *(const uint32_t*)(sAlo + o + 8);
                Al[mt][3] = *(const uint32_t*)(sAlo + o + 8 * 40 + 8);
            }
            #pragma unroll
            for (int nt = 0; nt < 4; nt++) {
                int o = (wn * 32 + nt * 8 + g) * 40 + kb + 2 * tq;
                Bh[nt][0] = *(const uint32_t*)(sBhi + o);
                Bh[nt][1] = *(const uint32_t*)(sBhi + o + 8);
                Bl[nt][0] = *(const uint32_t*)(sBlo + o);
                Bl[nt][1] = *(const uint32_t*)(sBlo + o + 8);
            }
            #pragma unroll
            for (int mt = 0; mt < 4; mt++)
                #pragma unroll
                for (int nt = 0; nt < 4; nt++) {
                    mma16816(acc[mt][nt], Ah[mt], Bh[nt]);
                    mma16816(acc[mt][nt], Ah[mt], Bl[nt]);
                    mma16816(acc[mt][nt], Al[mt], Bh[nt]);
                }
        }
        __syncthreads();                // bf16 tiles consumed before next split
    }

    // ---- epilogue: add bias, store f32 (full 32B sectors per (g,nt)) ----
    const int gate  = bn >> 2;
    const int jbase = (bn & 3) * 128 + wn * 32;
    #pragma unroll
    for (int nt = 0; nt < 4; nt++) {
        int j = jbase + nt * 8 + 2 * tq;
        int nglob = bn * 128 + wn * 32 + nt * 8 + 2 * tq;
        float b0 = bias[nglob], b1 = bias[nglob + 1];
        #pragma unroll
        for (int mt = 0; mt < 4; mt++) {
            int m = bm * 128 + wm * 64 + mt * 16 + g;
            float* p0 = g_xg2 + (((size_t)dir * 4 + gate) * 8192 + m) * HDIM + j;
            float* p1 = p0 + 8 * HDIM;   // row m+8
            *(float2*)p0 = make_float2(acc[mt][nt][0] + b0, acc[mt][nt][1] + b1);
            *(float2*)p1 = make_float2(acc[mt][nt][2] + b0, acc[mt][nt][3] + b1);
        }
    }
}

// ---------------------------------------------------------------------------
// Kernel 2: persistent BiLSTM recurrence on HMMA with SUB-GROUP barriers.
// 128 blocks = (dir, 32 chunks of 16 units -> 64 gate rows, 2 batch halves).
// Warp w's k-slice [64w,64w+64) is produced by chunks 4w..4w+3 (same dir,bh):
// block arrives at its slice counter; warp w polls counter w only, then
// proceeds independently (poll/LDG/MMA overlapped across warps).
// ---------------------------------------------------------------------------
__global__ void __launch_bounds__(256, 1) recur_kernel(
    const float* __restrict__ whhf, const float* __restrict__ whhb)
{
    __shared__ float part[8 * 64 * 17];   // [w][row 0..63][b 0..15] padded

    const int tid = threadIdx.x;
    const int w   = tid >> 5;
    const int lid = tid & 31;
    const int g   = lid >> 2;             // mma groupID
    const int tq  = lid & 3;              // mma threadID_in_group

    const int bid   = blockIdx.x;
    const int dir   = bid >> 6;
    const int sub   = bid & 63;
    const int chunk = sub >> 1;            // 0..31, 16 units each
    const int bh    = sub & 1;
    const int j0    = chunk * 16;

    // cell role: one (u, bt) per thread
    const int u  = tid & 15;
    const int bt = tid >> 4;

    int* my_cnt   = g_scnt + (((dir * 2 + bh) * 8) + (chunk >> 2)) * 32;  // arrive
    int* poll_cnt = g_scnt + (((dir * 2 + bh) * 8) + w) * 32;             // wait

    // ---- one-time: W fragments (hi/lo split) into registers ----
    const float* whh = dir ? whhb : whhf;
    uint32_t ahi[4][4][4], alo[4][4][4];   // [mt=gate][kt][reg]
    #pragma unroll
    for (int mt = 0; mt < 4; mt++)
        #pragma unroll
        for (int kt = 0; kt < 4; kt++)
            #pragma unroll
            for (int reg = 0; reg < 4; reg++) {
                int urow = g + (reg & 1) * 8;              // within 16-unit tile
                int grow = mt * HDIM + j0 + urow;          // row in W[2048]
                int k    = w * 64 + kt * 16 + 2 * tq + (reg >> 1) * 8;
                float v0 = whh[(size_t)grow * HDIM + k];
                float v1 = whh[(size_t)grow * HDIM + k + 1];
                __nv_bfloat16 h0 = __float2bfloat16(v0);
                __nv_bfloat16 h1 = __float2bfloat16(v1);
                __nv_bfloat16 l0 = __float2bfloat16(v0 - __bfloat162float(h0));
                __nv_bfloat16 l1 = __float2bfloat16(v1 - __bfloat162float(h1));
                ahi[mt][kt][reg] = (uint32_t)__bfloat16_as_ushort(h0)
                                 | ((uint32_t)__bfloat16_as_ushort(h1) << 16);
                alo[mt][kt][reg] = (uint32_t)__bfloat16_as_ushort(l0)
                                 | ((uint32_t)__bfloat16_as_ushort(l1) << 16);
            }

    float c = 0.f;                         // cell state (dir, j0+u, bh*16+bt)

    for (int step = 0; step < SEQ; ++step) {
        const int t = dir ? (SEQ - 1 - step) : step;

        // ---- arrive: all warps' frag stores ordered via syncthreads + release ----
        __syncthreads();                   // h-frag stores of prev step done CTA-wide
        if (tid == 0)
            asm volatile("red.release.gpu.global.add.s32 [%0], %1;" :: "l"(my_cnt), "r"(1) : "memory");

        // xg prefetch (independent of h; issues before the poll loop)
        float xgv[4];
        #pragma unroll
        for (int gate = 0; gate < 4; gate++)
            xgv[gate] = __ldg(g_xg2 +
                ((size_t)(dir * 4 + gate) * 8192 + (size_t)t * 32 + bh * 16 + bt) * HDIM + j0 + u);

        // ---- per-warp wait on own k-slice producers (4 arrivals/step) ----
        {
            const int target = 4 * (step + 1);
            int v;
            do {
                asm volatile("ld.acquire.gpu.global.s32 %0, [%1];" : "=r"(v) : "l"(poll_cnt) : "memory");
            } while (v < target);
        }

        // ---- load B fragments: 4 hi + 4 lo LDG.128 per thread ----
        const uint32_t slot = (step == 0) ? 1024u
            : (uint32_t)((dir * SEQ + (dir ? t + 1 : t - 1)) * 2 + bh);
        const uint4* bhp = (const uint4*)(g_hfrag_hi + (size_t)slot * 4096u) + (w * 4) * 32 + lid;
        const uint4* blp = (const uint4*)(g_hfrag_lo + (size_t)slot * 4096u) + (w * 4) * 32 + lid;
        uint32_t bhi[4][2][2], blo[4][2][2];
        #pragma unroll
        for (int kt = 0; kt < 4; kt++) {
            uint4 vh = bhp[kt * 32];
            uint4 vl = blp[kt * 32];
            bhi[kt][0][0] = vh.x; bhi[kt][0][1] = vh.y;
            bhi[kt][1][0] = vh.z; bhi[kt][1][1] = vh.w;
            blo[kt][0][0] = vl.x; blo[kt][0][1] = vl.y;
            blo[kt][1][0] = vl.z; blo[kt][1][1] = vl.w;
        }

        // ---- MMAs: (Whi+Wlo)(hhi+hlo) minus lo*lo ----
        float acc[4][2][4];
        #pragma unroll
        for (int mt = 0; mt < 4; mt++)
            #pragma unroll
            for (int nt = 0; nt < 2; nt++)
                #pragma unroll
                for (int q = 0; q < 4; q++) acc[mt][nt][q] = 0.f;
        #pragma unroll
        for (int kt = 0; kt < 4; kt++)
            #pragma unroll
            for (int mt = 0; mt < 4; mt++)
                #pragma unroll
                for (int nt = 0; nt < 2; nt++) {
                    mma16816(acc[mt][nt], ahi[mt][kt], bhi[kt][nt]);
                    mma16816(acc[mt][nt], ahi[mt][kt], blo[kt][nt]);
                    mma16816(acc[mt][nt], alo[mt][kt], bhi[kt][nt]);
                }

        // ---- write partials to smem ----
        #pragma unroll
        for (int mt = 0; mt < 4; mt++)
            #pragma unroll
            for (int nt = 0; nt < 2; nt++) {
                int row0 = mt * 16 + g;
                int col0 = nt * 8 + 2 * tq;
                part[(w * 64 + row0) * 17 + col0]         = acc[mt][nt][0];
                part[(w * 64 + row0) * 17 + col0 + 1]     = acc[mt][nt][1];
                part[(w * 64 + row0 + 8) * 17 + col0]     = acc[mt][nt][2];
                part[(w * 64 + row0 + 8) * 17 + col0 + 1] = acc[mt][nt][3];
            }
        __syncthreads();

        // ---- reduce across 8 k-slices + LSTM cell for (u, bt) ----
        float gi = xgv[0], gf = xgv[1], gg = xgv[2], go = xgv[3];
        #pragma unroll
        for (int kw = 0; kw < 8; kw++) {
            gi += part[(kw * 64 +  0 + u) * 17 + bt];
            gf += part[(kw * 64 + 16 + u) * 17 + bt];
            gg += part[(kw * 64 + 32 + u) * 17 + bt];
            go += part[(kw * 64 + 48 + u) * 17 + bt];
        }
        c = fsig(gf) * c + fsig(gi) * ftanh(gg);
        float h = fsig(go) * ftanh(c);

        g_hseq[((size_t)(dir * SEQ + t) * BATCH + bh * 16 + bt) * HDIM + j0 + u] = h;

        // ---- pack h into B-fragment words (pairs along u via shfl) ----
        float ho = __shfl_xor_sync(0xffffffffu, h, 1);   // partner u^1, same bt
        if ((u & 1) == 0) {
            __nv_bfloat16 hh0 = __float2bfloat16(h);
            __nv_bfloat16 hh1 = __float2bfloat16(ho);
            __nv_bfloat16 hl0 = __float2bfloat16(h  - __bfloat162float(hh0));
            __nv_bfloat16 hl1 = __float2bfloat16(ho - __bfloat162float(hh1));
            uint32_t whi = (uint32_t)__bfloat16_as_ushort(hh0)
                         | ((uint32_t)__bfloat16_as_ushort(hh1) << 16);
            uint32_t wlo = (uint32_t)__bfloat16_as_ushort(hl0)
                         | ((uint32_t)__bfloat16_as_ushort(hl1) << 16);
            int reg = u >> 3;
            int tq2 = (u & 7) >> 1;
            int nt2 = bt >> 3;
            int g2  = bt & 7;
            uint32_t slotW = (uint32_t)((dir * SEQ + t) * 2 + bh);
            size_t idx = (size_t)slotW * 4096u + (uint32_t)chunk * 128u
                       + (uint32_t)((g2 * 4 + tq2) * 4 + nt2 * 2 + reg);
            g_hfrag_hi[idx] = whi;
            g_hfrag_lo[idx] = wlo;
        }
    }
}

// ---------------------------------------------------------------------------
// Kernel 3: feats (unchanged)
// ---------------------------------------------------------------------------
__global__ void __launch_bounds__(256) feats_kernel(
    const float* __restrict__ w_out, const float* __restrict__ b_out)
{
    const int s = blockIdx.x;
    const int w = threadIdx.x >> 5;
    const int l = threadIdx.x & 31;

    for (int b = w; b < BATCH; b += 8) {
        const float* hf = g_hseq + ((size_t)(0 * SEQ + s) * BATCH + b) * HDIM;
        const float* hb = g_hseq + ((size_t)(1 * SEQ + s) * BATCH + b) * HDIM;
        float hv[32];
        #pragma unroll
        for (int i = 0; i < 16; i++) hv[i]      = hf[l + 32 * i];
        #pragma unroll
        for (int i = 0; i < 16; i++) hv[16 + i] = hb[l + 32 * i];
        for (int tag = 0; tag < TTAGS; tag++) {
            const float* wr = w_out + (size_t)tag * (2 * HDIM);
            float p = 0.f;
            #pragma unroll
            for (int i = 0; i < 16; i++) p = fmaf(hv[i],      wr[l + 32 * i],        p);
            #pragma unroll
            for (int i = 0; i < 16; i++) p = fmaf(hv[16 + i], wr[HDIM + l + 32 * i], p);
            #pragma unroll
            for (int o = 16; o; o >>= 1) p += __shfl_down_sync(0xffffffffu, p, o);
            if (l == 0) g_feats[(s * BATCH + b) * TTAGS + tag] = p + b_out[tag];
        }
    }
}

// ---------------------------------------------------------------------------
// Kernel 4: CRF forward (MUFU exp/log in the serial scan)
// ---------------------------------------------------------------------------
__global__ void __launch_bounds__(32) crf_kernel(
    const int* __restrict__ lengths, const float* __restrict__ trans,
    float* __restrict__ out)
{
    const int b = blockIdx.x;
    const int l = threadIdx.x;

    __shared__ float fb[SEQ * TTAGS];
    __shared__ float es[32];
    for (int i = l; i < SEQ * TTAGS; i += 32) {
        int s = i / TTAGS, tg = i - s * TTAGS;
        fb[i] = g_feats[(s * BATCH + b) * TTAGS + tg];
    }

    float et[TTAGS];
    if (l < TTAGS) {
        #pragma unroll
        for (int p = 0; p < TTAGS; p++) et[p] = __expf(trans[l * TTAGS + p]);
    }
    float fv = (l == START_TAG) ? 0.f : NEGV;
    es[l] = 0.f;
    __syncwarp();

    const int len = lengths[b];
    for (int s = 0; s < len; s++) {
        float v = (l < TTAGS) ? fv : -1e30f;
        #pragma unroll
        for (int o = 8; o; o >>= 1) v = fmaxf(v, __shfl_xor_sync(0xffffffffu, v, o));
        float e = (l < TTAGS) ? __expf(fv - v) : 0.f;
        es[l] = e;
        __syncwarp();
        float sa = 0.f, sb = 0.f;
        #pragma unroll
        for (int p = 0; p < TTAGS; p += 2) {
            sa = fmaf(es[p],     et[p],     sa);
            sb = fmaf(es[p + 1], et[p + 1], sb);
        }
        if (l < TTAGS) fv = v + __logf(sa + sb) + fb[s * TTAGS + l];
        __syncwarp();
    }

    float term = (l < TTAGS) ? (fv + trans[STOP_TAG * TTAGS + l]) : -1e30f;
    float mx = term;
    #pragma unroll
    for (int o = 16; o; o >>= 1) mx = fmaxf(mx, __shfl_xor_sync(0xffffffffu, mx, o));
    float e = (l < TTAGS) ? __expf(term - mx) : 0.f;
    #pragma unroll
    for (int o = 16; o; o >>= 1) e += __shfl_xor_sync(0xffffffffu, e, o);
    if (l == 0) out[b] = (mx + __logf(e)) / (float)len;
}

// ---------------------------------------------------------------------------
extern "C" void kernel_launch(void* const* d_in, const int* in_sizes, int n_in,
                              void* d_out, int out_size)
{
    const int*   tokens  = (const int*)  d_in[0];
    const int*   lengths = (const int*)  d_in[1];
    const float* emb     = (const float*)d_in[2];
    const float* w_ih_f  = (const float*)d_in[3];
    const float* w_hh_f  = (const float*)d_in[4];
    const float* b_f     = (const float*)d_in[5];
    const float* w_ih_b  = (const float*)d_in[6];
    const float* w_hh_b  = (const float*)d_in[7];
    const float* b_b     = (const float*)d_in[8];
    const float* w_out   = (const float*)d_in[9];
    const float* b_out   = (const float*)d_in[10];
    const float* trans   = (const float*)d_in[11];
    float* out = (float*)d_out;

    cudaFuncSetAttribute(xg_kernel, cudaFuncAttributeMaxDynamicSharedMemorySize, XG_SMEM);

    dummy_kernel<<<1, 32>>>();
    dummy_kernel<<<1, 32>>>();
    xg_kernel<<<dim3(64, 16, 2), 256, XG_SMEM>>>(tokens, emb, w_ih_f, b_f, w_ih_b, b_b);
    recur_kernel<<<128, 256>>>(w_hh_f, w_hh_b);
    feats_kernel<<<SEQ, 256>>>(w_out, b_out);
    crf_kernel<<<BATCH, 32>>>(lengths, trans, out);
}